// round 1
// baseline (speedup 1.0000x reference)
#include <cuda_runtime.h>
#include <cuda_bf16.h>

// ---------------- problem constants (fixed shapes) ----------------
#define NN 50000     // nodes
#define NE 800000    // edges
#define DIN 128      // input feature dim
#define DH  256      // hidden dim (H1)
#define H2D 128      // readout hidden dim
#define NG  256      // num graphs

// ---------------- device scratch (static, allocation-free) ----------------
__device__ int   g_deg[NN];
__device__ int   g_rowptr[NN + 1];
__device__ int   g_cursor[NN];
__device__ int   g_col[NE];
__device__ float g_a1[(size_t)NN * DIN];   // mean-agg of input h
__device__ float g_h1[(size_t)NN * DH];    // relu(a1@W1+b1)
__device__ float g_a2[(size_t)NN * DH];    // mean-agg of h1
__device__ float g_h2[(size_t)NN * DH];    // relu(a2@W2+b2)
__device__ float g_hg[NG * DH];            // per-graph means

// ---------------- CSR build ----------------
__global__ void zero_deg_kernel(int n) {
    int i = blockIdx.x * blockDim.x + threadIdx.x;
    if (i < n) g_deg[i] = 0;
}

__global__ void hist_kernel(const int* __restrict__ dst, int e) {
    int i = blockIdx.x * blockDim.x + threadIdx.x;
    if (i < e) atomicAdd(&g_deg[dst[i]], 1);
}

// single-block exclusive scan over g_deg -> g_rowptr (and copy to g_cursor)
__global__ void scan_kernel(int n) {
    __shared__ int sums[1024];
    const int t = threadIdx.x;
    const int C = (n + 1023) / 1024;
    const int start = t * C;
    const int end = min(start + C, n);

    int local = 0;
    for (int i = start; i < end; i++) local += g_deg[i];
    sums[t] = local;
    __syncthreads();

    // Hillis-Steele inclusive scan
    for (int off = 1; off < 1024; off <<= 1) {
        int v = (t >= off) ? sums[t - off] : 0;
        __syncthreads();
        sums[t] += v;
        __syncthreads();
    }

    int run = sums[t] - local;  // exclusive base for this thread's chunk
    for (int i = start; i < end; i++) {
        g_rowptr[i] = run;
        g_cursor[i] = run;
        run += g_deg[i];
    }
    if (start < n && end == n) g_rowptr[n] = run;
}

__global__ void fill_kernel(const int* __restrict__ src, const int* __restrict__ dst, int e) {
    int i = blockIdx.x * blockDim.x + threadIdx.x;
    if (i < e) {
        int pos = atomicAdd(&g_cursor[dst[i]], 1);
        g_col[pos] = src[i];
    }
}

// ---------------- mean aggregation (gather over CSR) ----------------
// one block per node, D threads: thread t owns feature column t.
template <int D>
__global__ void agg_kernel(const float* __restrict__ in, float* __restrict__ out) {
    const int n = blockIdx.x;
    const int t = threadIdx.x;
    const int s = g_rowptr[n];
    const int e = g_rowptr[n + 1];
    float acc = 0.f;
    for (int j = s; j < e; j++) {
        int sn = g_col[j];
        acc += __ldg(&in[(size_t)sn * D + t]);
    }
    float d = (float)(e - s);
    out[(size_t)n * D + t] = acc / fmaxf(d, 1.f);
}

// ---------------- SGEMM with fused bias + optional ReLU ----------------
// C[M,N] = A[M,K] @ B[K,N] + bias; BM=128, BN=128, BK=8, TM=TN=8, 256 threads.
template <bool RELU>
__global__ __launch_bounds__(256)
void sgemm_bias_kernel(int M, int N, int K,
                       const float* __restrict__ A,
                       const float* __restrict__ B,
                       const float* __restrict__ bias,
                       float* __restrict__ C) {
    constexpr int BM = 128, BN = 128, BK = 8, TM = 8, TN = 8;
    __shared__ float As[BK][BM];
    __shared__ float Bs[BK][BN];

    const int tid = threadIdx.x;
    const int tx = tid % (BN / TN);   // 0..15
    const int ty = tid / (BN / TN);   // 0..15
    const int rowBase = blockIdx.y * BM;
    const int colBase = blockIdx.x * BN;

    // A tile load mapping: 128 rows x 8 cols = 256 float4 (2 per row)
    const int aRow = tid >> 1;            // 0..127
    const int aCol = (tid & 1) * 4;       // 0 or 4
    // B tile load mapping: 8 rows x 128 cols = 256 float4 (32 per row)
    const int bRow = tid >> 5;            // 0..7
    const int bCol = (tid & 31) * 4;      // 0..124

    float acc[TM][TN];
#pragma unroll
    for (int i = 0; i < TM; i++)
#pragma unroll
        for (int j = 0; j < TN; j++) acc[i][j] = 0.f;

    for (int k0 = 0; k0 < K; k0 += BK) {
        float4 av = make_float4(0.f, 0.f, 0.f, 0.f);
        int gr = rowBase + aRow;
        if (gr < M) av = *(const float4*)&A[(size_t)gr * K + k0 + aCol];
        As[aCol + 0][aRow] = av.x;
        As[aCol + 1][aRow] = av.y;
        As[aCol + 2][aRow] = av.z;
        As[aCol + 3][aRow] = av.w;

        float4 bv = *(const float4*)&B[(size_t)(k0 + bRow) * N + colBase + bCol];
        *(float4*)&Bs[bRow][bCol] = bv;
        __syncthreads();

#pragma unroll
        for (int kk = 0; kk < BK; kk++) {
            float ar[TM], br[TN];
#pragma unroll
            for (int i = 0; i < TM; i++) ar[i] = As[kk][ty * TM + i];
#pragma unroll
            for (int j = 0; j < TN; j++) br[j] = Bs[kk][tx * TN + j];
#pragma unroll
            for (int i = 0; i < TM; i++)
#pragma unroll
                for (int j = 0; j < TN; j++) acc[i][j] += ar[i] * br[j];
        }
        __syncthreads();
    }

    float bj[TN];
#pragma unroll
    for (int j = 0; j < TN; j++) bj[j] = bias[colBase + tx * TN + j];

#pragma unroll
    for (int i = 0; i < TM; i++) {
        int row = rowBase + ty * TM + i;
        if (row >= M) break;
        float* crow = &C[(size_t)row * N + colBase + tx * TN];
#pragma unroll
        for (int j = 0; j < TN; j++) {
            float v = acc[i][j] + bj[j];
            if (RELU) v = fmaxf(v, 0.f);
            crow[j] = v;
        }
    }
}

// ---------------- per-graph mean readout (graph_ids sorted) ----------------
__global__ void readout_kernel(const int* __restrict__ gid, int n) {
    const int g = blockIdx.x;
    const int t = threadIdx.x;  // 256 threads, one per feature column
    __shared__ int s_lo, s_hi;
    if (t == 0) {
        int lo = 0, hi = n;
        while (lo < hi) { int m = (lo + hi) >> 1; if (gid[m] < g) lo = m + 1; else hi = m; }
        s_lo = lo;
        hi = n;
        while (lo < hi) { int m = (lo + hi) >> 1; if (gid[m] <= g) lo = m + 1; else hi = m; }
        s_hi = lo;
    }
    __syncthreads();
    float acc = 0.f;
    for (int nd = s_lo; nd < s_hi; nd++) acc += g_h2[(size_t)nd * DH + t];
    float cnt = (float)(s_hi - s_lo);
    g_hg[g * DH + t] = acc / fmaxf(cnt, 1.f);
}

// ---------------- final MLP head: out = (hg@Wr1+br1)@Wr2+br2 ----------------
__global__ void mlp_kernel(const float* __restrict__ Wr1, const float* __restrict__ br1,
                           const float* __restrict__ Wr2, const float* __restrict__ br2,
                           float* __restrict__ out) {
    const int g = blockIdx.x;
    const int t = threadIdx.x;  // 128 threads (H2)
    float acc = br1[t];
    const float* hg = &g_hg[g * DH];
    for (int k = 0; k < DH; k++) acc += hg[k] * Wr1[k * H2D + t];
    // no ReLU on the readout hidden layer (matches reference)
    __shared__ float red[H2D];
    red[t] = acc * Wr2[t];
    __syncthreads();
    for (int s = H2D / 2; s > 0; s >>= 1) {
        if (t < s) red[t] += red[t + s];
        __syncthreads();
    }
    if (t == 0) out[g] = red[0] + br2[0];
}

// ---------------- launch ----------------
extern "C" void kernel_launch(void* const* d_in, const int* in_sizes, int n_in,
                              void* d_out, int out_size) {
    const float* h   = (const float*)d_in[0];
    const int*   src = (const int*)d_in[1];
    const int*   dst = (const int*)d_in[2];
    const int*   gid = (const int*)d_in[3];
    const float* W1  = (const float*)d_in[4];
    const float* b1  = (const float*)d_in[5];
    const float* W2  = (const float*)d_in[6];
    const float* b2  = (const float*)d_in[7];
    const float* Wr1 = (const float*)d_in[8];
    const float* br1 = (const float*)d_in[9];
    const float* Wr2 = (const float*)d_in[10];
    const float* br2 = (const float*)d_in[11];
    float* out = (float*)d_out;

    const int N = in_sizes[0] / DIN;   // 50000
    const int E = in_sizes[1];         // 800000

    // device scratch pointers (symbol lookup is not an allocation)
    float *pa1, *ph1, *pa2, *ph2;
    cudaGetSymbolAddress((void**)&pa1, g_a1);
    cudaGetSymbolAddress((void**)&ph1, g_h1);
    cudaGetSymbolAddress((void**)&pa2, g_a2);
    cudaGetSymbolAddress((void**)&ph2, g_h2);

    // 1) CSR build (dst-indexed)
    zero_deg_kernel<<<(N + 255) / 256, 256>>>(N);
    hist_kernel<<<(E + 255) / 256, 256>>>(dst, E);
    scan_kernel<<<1, 1024>>>(N);
    fill_kernel<<<(E + 255) / 256, 256>>>(src, dst, E);

    // 2) layer 1: mean-agg then GEMM+bias+ReLU  [N,128] -> [N,256]
    agg_kernel<DIN><<<N, DIN>>>(h, pa1);
    {
        dim3 grid(DH / 128, (N + 127) / 128);
        sgemm_bias_kernel<true><<<grid, 256>>>(N, DH, DIN, pa1, W1, b1, ph1);
    }

    // 3) layer 2: mean-agg then GEMM+bias+ReLU  [N,256] -> [N,256]
    agg_kernel<DH><<<N, DH>>>(ph1, pa2);
    {
        dim3 grid(DH / 128, (N + 127) / 128);
        sgemm_bias_kernel<true><<<grid, 256>>>(N, DH, DH, pa2, W2, b2, ph2);
    }

    // 4) per-graph mean readout + MLP head
    readout_kernel<<<NG, DH>>>(gid, N);
    mlp_kernel<<<NG, H2D>>>(Wr1, br1, Wr2, br2, out);
}

// round 3
// speedup vs baseline: 1.2585x; 1.2585x over previous
#include <cuda_runtime.h>
#include <cuda_bf16.h>
#include <mma.h>

using namespace nvcuda;

// ---------------- problem constants (fixed shapes) ----------------
#define NN 50000      // nodes
#define NN_PAD 50048  // padded to 391*128 for wmma tiles
#define NE 800000     // edges
#define DIN 128       // input feature dim
#define DH  256       // hidden dim (H1)
#define H2D 128       // readout hidden dim
#define NG  256       // num graphs

// ---------------- device scratch (static, allocation-free) ----------------
__device__ int   g_deg[NN];
__device__ int   g_rowptr[NN + 1];
__device__ int   g_cursor[NN];
__device__ int   g_col[NE];
__device__ float g_a1[(size_t)NN_PAD * DIN];   // mean-agg of input h
__device__ float g_h1[(size_t)NN_PAD * DH];    // a1@W1 (raw, no bias/relu)
__device__ float g_a2[(size_t)NN_PAD * DH];    // mean-agg of relu(h1+b1)
__device__ float g_h2[(size_t)NN_PAD * DH];    // a2@W2 (raw, no bias/relu)
__device__ float g_hg[NG * DH];                // per-graph means

// ---------------- CSR build ----------------
__global__ void zero_deg_kernel(int n) {
    int i = blockIdx.x * blockDim.x + threadIdx.x;
    if (i < n) g_deg[i] = 0;
}

__global__ void hist_kernel(const int* __restrict__ dst, int e) {
    int i = blockIdx.x * blockDim.x + threadIdx.x;
    if (i < e) atomicAdd(&g_deg[dst[i]], 1);
}

// single-block exclusive scan over g_deg -> g_rowptr (and copy to g_cursor)
__global__ void scan_kernel(int n) {
    __shared__ int sums[1024];
    const int t = threadIdx.x;
    const int C = (n + 1023) / 1024;
    const int start = t * C;
    const int end = min(start + C, n);

    int local = 0;
    for (int i = start; i < end; i++) local += g_deg[i];
    sums[t] = local;
    __syncthreads();

    for (int off = 1; off < 1024; off <<= 1) {
        int v = (t >= off) ? sums[t - off] : 0;
        __syncthreads();
        sums[t] += v;
        __syncthreads();
    }

    int run = sums[t] - local;
    for (int i = start; i < end; i++) {
        g_rowptr[i] = run;
        g_cursor[i] = run;
        run += g_deg[i];
    }
    if (start < n && end == n) g_rowptr[n] = run;
}

__global__ void fill_kernel(const int* __restrict__ src, const int* __restrict__ dst, int e) {
    int i = blockIdx.x * blockDim.x + threadIdx.x;
    if (i < e) {
        int pos = atomicAdd(&g_cursor[dst[i]], 1);
        g_col[pos] = src[i];
    }
}

// ---------------- mean aggregation (gather over CSR) ----------------
// one block per node, D threads: thread t owns feature column t.
// MODE 0: acc += in[row][t]          (raw input)
// MODE 1: acc += relu(in[row][t] + bias[t])   (fused GEMM epilogue)
template <int D, int MODE>
__global__ void agg_kernel(const float* __restrict__ in,
                           const float* __restrict__ bias,
                           float* __restrict__ out) {
    const int n = blockIdx.x;
    const int t = threadIdx.x;
    const int s = g_rowptr[n];
    const int e = g_rowptr[n + 1];
    float b = (MODE == 1) ? bias[t] : 0.f;
    float acc = 0.f;
    for (int j = s; j < e; j++) {
        int sn = g_col[j];
        float v = __ldg(&in[(size_t)sn * D + t]);
        if (MODE == 1) v = fmaxf(v + b, 0.f);
        acc += v;
    }
    float d = (float)(e - s);
    out[(size_t)n * D + t] = acc / fmaxf(d, 1.f);
}

// ---------------- TF32 tensor-core GEMM ----------------
// C[M,N] = A[M,K] @ B[K,N]  (raw, no epilogue; bias/relu fused downstream)
// BM=BN=128, BK=32. 256 threads = 8 warps in 2x4 grid; each warp 64x32
// (4x2 fragments of m16n16k8 tf32). M must be a multiple of 128 (padded).
__global__ __launch_bounds__(256, 2)
void wmma_gemm_kernel(int M, int N, int K,
                      const float* __restrict__ A,
                      const float* __restrict__ B,
                      float* __restrict__ C) {
    constexpr int BM = 128, BN = 128, BK = 32;
    constexpr int LDA = BK + 4;    // 36 floats (144B, 16B-aligned stride)
    constexpr int LDB = BN + 4;    // 132 floats (528B, 16B-aligned stride)
    __shared__ float As[BM][LDA];
    __shared__ float Bs[BK][LDB];

    const int tid = threadIdx.x;
    const int warpId = tid >> 5;
    const int warpRow = warpId >> 2;   // 0..1 -> rows warpRow*64
    const int warpCol = warpId & 3;    // 0..3 -> cols warpCol*32
    const int rowBase = blockIdx.y * BM;
    const int colBase = blockIdx.x * BN;

    wmma::fragment<wmma::accumulator, 16, 16, 8, float> acc[4][2];
#pragma unroll
    for (int i = 0; i < 4; i++)
#pragma unroll
        for (int j = 0; j < 2; j++) wmma::fill_fragment(acc[i][j], 0.f);

    for (int k0 = 0; k0 < K; k0 += BK) {
        // Load A tile: 128x32 = 1024 float4, 4 per thread
#pragma unroll
        for (int l = 0; l < 4; l++) {
            int lin = tid + l * 256;
            int r = lin >> 3;            // 0..127
            int c4 = (lin & 7) * 4;      // 0..28
            float4 v = *(const float4*)&A[(size_t)(rowBase + r) * K + k0 + c4];
            *(float4*)&As[r][c4] = v;
        }
        // Load B tile: 32x128 = 1024 float4, 4 per thread
#pragma unroll
        for (int l = 0; l < 4; l++) {
            int lin = tid + l * 256;
            int r = lin >> 5;            // 0..31
            int c4 = (lin & 31) * 4;     // 0..124
            float4 v = *(const float4*)&B[(size_t)(k0 + r) * N + colBase + c4];
            *(float4*)&Bs[r][c4] = v;
        }
        __syncthreads();

#pragma unroll
        for (int kk = 0; kk < BK; kk += 8) {
            wmma::fragment<wmma::matrix_a, 16, 16, 8, wmma::precision::tf32, wmma::row_major> a[4];
            wmma::fragment<wmma::matrix_b, 16, 16, 8, wmma::precision::tf32, wmma::row_major> b[2];
#pragma unroll
            for (int i = 0; i < 4; i++) {
                wmma::load_matrix_sync(a[i], &As[warpRow * 64 + i * 16][kk], LDA);
#pragma unroll
                for (int t = 0; t < a[i].num_elements; t++)
                    a[i].x[t] = wmma::__float_to_tf32(a[i].x[t]);
            }
#pragma unroll
            for (int j = 0; j < 2; j++) {
                wmma::load_matrix_sync(b[j], &Bs[kk][warpCol * 32 + j * 16], LDB);
#pragma unroll
                for (int t = 0; t < b[j].num_elements; t++)
                    b[j].x[t] = wmma::__float_to_tf32(b[j].x[t]);
            }
#pragma unroll
            for (int i = 0; i < 4; i++)
#pragma unroll
                for (int j = 0; j < 2; j++)
                    wmma::mma_sync(acc[i][j], a[i], b[j], acc[i][j]);
        }
        __syncthreads();
    }

#pragma unroll
    for (int i = 0; i < 4; i++)
#pragma unroll
        for (int j = 0; j < 2; j++) {
            int r = rowBase + warpRow * 64 + i * 16;
            int c = colBase + warpCol * 32 + j * 16;
            wmma::store_matrix_sync(&C[(size_t)r * N + c], acc[i][j], N, wmma::mem_row_major);
        }
}

// ---------------- per-graph mean readout (graph_ids sorted) ----------------
// sums relu(h2raw + b2[col]) over the graph's node range.
__global__ void readout_kernel(const int* __restrict__ gid,
                               const float* __restrict__ b2, int n) {
    const int g = blockIdx.x;
    const int t = threadIdx.x;  // 256 threads, one per feature column
    __shared__ int s_lo, s_hi;
    if (t == 0) {
        int lo = 0, hi = n;
        while (lo < hi) { int m = (lo + hi) >> 1; if (gid[m] < g) lo = m + 1; else hi = m; }
        s_lo = lo;
        hi = n;
        while (lo < hi) { int m = (lo + hi) >> 1; if (gid[m] <= g) lo = m + 1; else hi = m; }
        s_hi = lo;
    }
    __syncthreads();
    const float b = b2[t];
    float acc = 0.f;
    for (int nd = s_lo; nd < s_hi; nd++)
        acc += fmaxf(g_h2[(size_t)nd * DH + t] + b, 0.f);
    float cnt = (float)(s_hi - s_lo);
    g_hg[g * DH + t] = acc / fmaxf(cnt, 1.f);
}

// ---------------- final MLP head: out = (hg@Wr1+br1)@Wr2+br2 ----------------
__global__ void mlp_kernel(const float* __restrict__ Wr1, const float* __restrict__ br1,
                           const float* __restrict__ Wr2, const float* __restrict__ br2,
                           float* __restrict__ out) {
    const int g = blockIdx.x;
    const int t = threadIdx.x;  // 128 threads (H2)
    float acc = br1[t];
    const float* hg = &g_hg[g * DH];
    for (int k = 0; k < DH; k++) acc += hg[k] * Wr1[k * H2D + t];
    __shared__ float red[H2D];
    red[t] = acc * Wr2[t];
    __syncthreads();
    for (int s = H2D / 2; s > 0; s >>= 1) {
        if (t < s) red[t] += red[t + s];
        __syncthreads();
    }
    if (t == 0) out[g] = red[0] + br2[0];
}

// ---------------- launch ----------------
extern "C" void kernel_launch(void* const* d_in, const int* in_sizes, int n_in,
                              void* d_out, int out_size) {
    const float* h   = (const float*)d_in[0];
    const int*   src = (const int*)d_in[1];
    const int*   dst = (const int*)d_in[2];
    const int*   gid = (const int*)d_in[3];
    const float* W1  = (const float*)d_in[4];
    const float* b1  = (const float*)d_in[5];
    const float* W2  = (const float*)d_in[6];
    const float* b2  = (const float*)d_in[7];
    const float* Wr1 = (const float*)d_in[8];
    const float* br1 = (const float*)d_in[9];
    const float* Wr2 = (const float*)d_in[10];
    const float* br2 = (const float*)d_in[11];
    float* out = (float*)d_out;

    const int N = in_sizes[0] / DIN;   // 50000
    const int E = in_sizes[1];         // 800000

    float *pa1, *ph1, *pa2, *ph2;
    cudaGetSymbolAddress((void**)&pa1, g_a1);
    cudaGetSymbolAddress((void**)&ph1, g_h1);
    cudaGetSymbolAddress((void**)&pa2, g_a2);
    cudaGetSymbolAddress((void**)&ph2, g_h2);

    // 1) CSR build (dst-indexed)
    zero_deg_kernel<<<(N + 255) / 256, 256>>>(N);
    hist_kernel<<<(E + 255) / 256, 256>>>(dst, E);
    scan_kernel<<<1, 1024>>>(N);
    fill_kernel<<<(E + 255) / 256, 256>>>(src, dst, E);

    // 2) layer 1: mean-agg then tf32 GEMM  [N,128]@[128,256]
    agg_kernel<DIN, 0><<<N, DIN>>>(h, nullptr, pa1);
    {
        dim3 grid(DH / 128, NN_PAD / 128);
        wmma_gemm_kernel<<<grid, 256>>>(NN_PAD, DH, DIN, pa1, W1, ph1);
    }

    // 3) layer 2: mean-agg (fused relu(x+b1)) then tf32 GEMM  [N,256]@[256,256]
    agg_kernel<DH, 1><<<N, DH>>>(ph1, b1, pa2);
    {
        dim3 grid(DH / 128, NN_PAD / 128);
        wmma_gemm_kernel<<<grid, 256>>>(NN_PAD, DH, DH, pa2, W2, ph2);
    }

    // 4) per-graph mean readout (fused relu(x+b2)) + MLP head
    readout_kernel<<<NG, DH>>>(gid, b2, N);
    mlp_kernel<<<NG, H2D>>>(Wr1, br1, Wr2, br2, out);
}

// round 7
// speedup vs baseline: 1.5451x; 1.2278x over previous
#include <cstdint>
#include <cuda_runtime.h>
#include <cuda_bf16.h>
#include <mma.h>

using namespace nvcuda;

// ---------------- problem constants (fixed shapes) ----------------
#define NN 50000      // nodes
#define NN_PAD 50048  // padded to 391*128 for wmma tiles
#define NE 800000     // edges
#define DIN 128       // input feature dim
#define DH  256       // hidden dim (H1)
#define H2D 128       // readout hidden dim
#define NG  256       // num graphs

// ---------------- device scratch (static, allocation-free) ----------------
__device__ int   g_deg[NN];
__device__ int   g_rowptr[NN + 1];
__device__ int   g_cursor[NN];
__device__ int   g_col[NE];
__device__ float g_a1[(size_t)NN_PAD * DIN];   // mean-agg of input h (tf32-rounded)
__device__ float g_h1[(size_t)NN_PAD * DH];    // a1@W1 (raw fp32)
__device__ float g_a2[(size_t)NN_PAD * DH];    // mean-agg of relu(h1+b1) (tf32-rounded)
__device__ float g_h2[(size_t)NN_PAD * DH];    // a2@W2 (raw fp32)
__device__ float g_hg[NG * DH];                // per-graph means
__device__ float g_w1r[DIN * DH];              // tf32-rounded W1
__device__ float g_w2r[DH * DH];               // tf32-rounded W2

// ---------------- helpers ----------------
__device__ __forceinline__ float tf32r(float x) {
    asm("cvt.rna.tf32.f32 %0, %0;" : "+f"(x));
    return x;
}
__device__ __forceinline__ void cp_async16(void* smem, const void* gmem) {
    unsigned int s = (unsigned int)__cvta_generic_to_shared(smem);
    asm volatile("cp.async.cg.shared.global [%0], [%1], 16;\n" :: "r"(s), "l"(gmem));
}
__device__ __forceinline__ void cp_commit() {
    asm volatile("cp.async.commit_group;\n");
}
__device__ __forceinline__ void cp_wait1() {
    asm volatile("cp.async.wait_group 1;\n");
}
__device__ __forceinline__ void cp_wait0() {
    asm volatile("cp.async.wait_group 0;\n");
}

// ---------------- CSR build ----------------
__global__ void zero_deg_kernel(int n) {
    int i = blockIdx.x * blockDim.x + threadIdx.x;
    if (i < n) g_deg[i] = 0;
}

__global__ void hist_kernel(const int* __restrict__ dst, int e) {
    int i = blockIdx.x * blockDim.x + threadIdx.x;
    if (i < e) atomicAdd(&g_deg[dst[i]], 1);
}

__global__ void scan_kernel(int n) {
    __shared__ int sums[1024];
    const int t = threadIdx.x;
    const int C = (n + 1023) / 1024;
    const int start = t * C;
    const int end = min(start + C, n);

    int local = 0;
    for (int i = start; i < end; i++) local += g_deg[i];
    sums[t] = local;
    __syncthreads();

    for (int off = 1; off < 1024; off <<= 1) {
        int v = (t >= off) ? sums[t - off] : 0;
        __syncthreads();
        sums[t] += v;
        __syncthreads();
    }

    int run = sums[t] - local;
    for (int i = start; i < end; i++) {
        g_rowptr[i] = run;
        g_cursor[i] = run;
        run += g_deg[i];
    }
    if (start < n && end == n) g_rowptr[n] = run;
}

__global__ void fill_kernel(const int* __restrict__ src, const int* __restrict__ dst, int e) {
    int i = blockIdx.x * blockDim.x + threadIdx.x;
    if (i < e) {
        int pos = atomicAdd(&g_cursor[dst[i]], 1);
        g_col[pos] = src[i];
    }
}

// ---------------- weight pre-rounding to tf32 ----------------
__global__ void round_w_kernel(const float* __restrict__ w, float* __restrict__ out, int n) {
    int i = blockIdx.x * blockDim.x + threadIdx.x;
    if (i < n) out[i] = tf32r(w[i]);
}

// ---------------- mean aggregation (gather over CSR, warp per node) ----------------
// MODE 0: acc += in[row][c]
// MODE 1: acc += relu(in[row][c] + bias[c])   (fused GEMM epilogue)
// Output is tf32-rounded (it feeds a tf32 GEMM).
template <int D, int MODE>
__global__ void agg_kernel(const float* __restrict__ in,
                           const float* __restrict__ bias,
                           float* __restrict__ out) {
    constexpr int V = D / 128;  // float4s per lane (1 or 2)
    const int warp = (blockIdx.x * blockDim.x + threadIdx.x) >> 5;
    if (warp >= NN) return;
    const int lane = threadIdx.x & 31;

    const int s = g_rowptr[warp];
    const int e = g_rowptr[warp + 1];

    float4 acc[V];
    float4 bv[V];
#pragma unroll
    for (int v = 0; v < V; v++) {
        acc[v] = make_float4(0.f, 0.f, 0.f, 0.f);
        if (MODE == 1) bv[v] = __ldg(&((const float4*)bias)[lane + v * 32]);
    }

    int j = s;
    for (; j + 1 < e; j += 2) {
        const int s0 = g_col[j];
        const int s1 = g_col[j + 1];
        const float4* r0 = (const float4*)&in[(size_t)s0 * D];
        const float4* r1 = (const float4*)&in[(size_t)s1 * D];
#pragma unroll
        for (int v = 0; v < V; v++) {
            float4 x = __ldg(&r0[lane + v * 32]);
            float4 y = __ldg(&r1[lane + v * 32]);
            if (MODE == 1) {
                x.x = fmaxf(x.x + bv[v].x, 0.f); x.y = fmaxf(x.y + bv[v].y, 0.f);
                x.z = fmaxf(x.z + bv[v].z, 0.f); x.w = fmaxf(x.w + bv[v].w, 0.f);
                y.x = fmaxf(y.x + bv[v].x, 0.f); y.y = fmaxf(y.y + bv[v].y, 0.f);
                y.z = fmaxf(y.z + bv[v].z, 0.f); y.w = fmaxf(y.w + bv[v].w, 0.f);
            }
            acc[v].x += x.x + y.x; acc[v].y += x.y + y.y;
            acc[v].z += x.z + y.z; acc[v].w += x.w + y.w;
        }
    }
    if (j < e) {
        const int s0 = g_col[j];
        const float4* r0 = (const float4*)&in[(size_t)s0 * D];
#pragma unroll
        for (int v = 0; v < V; v++) {
            float4 x = __ldg(&r0[lane + v * 32]);
            if (MODE == 1) {
                x.x = fmaxf(x.x + bv[v].x, 0.f); x.y = fmaxf(x.y + bv[v].y, 0.f);
                x.z = fmaxf(x.z + bv[v].z, 0.f); x.w = fmaxf(x.w + bv[v].w, 0.f);
            }
            acc[v].x += x.x; acc[v].y += x.y; acc[v].z += x.z; acc[v].w += x.w;
        }
    }

    const float inv = 1.f / fmaxf((float)(e - s), 1.f);
#pragma unroll
    for (int v = 0; v < V; v++) {
        float4 o;
        o.x = tf32r(acc[v].x * inv);
        o.y = tf32r(acc[v].y * inv);
        o.z = tf32r(acc[v].z * inv);
        o.w = tf32r(acc[v].w * inv);
        ((float4*)&out[(size_t)warp * D])[lane + v * 32] = o;
    }
}

// ---------------- TF32 tensor-core GEMM (double-buffered cp.async) ----------------
// C[M,256] = A[M,K] @ B[K,256]; A,B pre-rounded to tf32. M multiple of 128.
// BM=BN=128, BK=32; 8 warps (2x4), warp tile 64x32 = 4x2 m16n16k8 frags.
template <int K>
__global__ __launch_bounds__(256, 2)
void gemm_tf32_kernel(const float* __restrict__ A,
                      const float* __restrict__ B,
                      float* __restrict__ C) {
    constexpr int BM = 128, BN = 128, BK = 32;
    constexpr int LDA = BK + 4;    // 36 floats = 144B (16B multiple)
    constexpr int LDB = BN + 4;    // 132 floats = 528B (16B multiple)
    constexpr int NT = K / BK;     // 4 or 8 K-tiles
    constexpr int NB = 256;        // B row stride (DH)
    __shared__ float As[2][BM][LDA];
    __shared__ float Bs[2][BK][LDB];

    const int tid = threadIdx.x;
    const int warpId = tid >> 5;
    const int warpRow = warpId >> 2;   // 0..1
    const int warpCol = warpId & 3;    // 0..3
    const int rowBase = blockIdx.y * BM;
    const int colBase = blockIdx.x * BN;

    const int aR = tid >> 3;           // 0..31 (+l*32)
    const int aC = (tid & 7) * 4;      // 0..28
    const int bR = tid >> 5;           // 0..7 (+l*8)
    const int bC = (tid & 31) * 4;     // 0..124

    auto load_tile = [&](int k0, int buf) {
#pragma unroll
        for (int l = 0; l < 4; l++) {
            int r = l * 32 + aR;
            cp_async16(&As[buf][r][aC], &A[(size_t)(rowBase + r) * K + k0 + aC]);
        }
#pragma unroll
        for (int l = 0; l < 4; l++) {
            int r = l * 8 + bR;
            cp_async16(&Bs[buf][r][bC], &B[(size_t)(k0 + r) * NB + colBase + bC]);
        }
        cp_commit();
    };

    wmma::fragment<wmma::accumulator, 16, 16, 8, float> acc[4][2];
#pragma unroll
    for (int i = 0; i < 4; i++)
#pragma unroll
        for (int j = 0; j < 2; j++) wmma::fill_fragment(acc[i][j], 0.f);

    load_tile(0, 0);

#pragma unroll
    for (int t = 0; t < NT; t++) {
        const int cur = t & 1;
        if (t + 1 < NT) {
            load_tile((t + 1) * BK, cur ^ 1);
            cp_wait1();
        } else {
            cp_wait0();
        }
        __syncthreads();

#pragma unroll
        for (int kk = 0; kk < BK; kk += 8) {
            wmma::fragment<wmma::matrix_a, 16, 16, 8, wmma::precision::tf32, wmma::row_major> a[4];
            wmma::fragment<wmma::matrix_b, 16, 16, 8, wmma::precision::tf32, wmma::row_major> b[2];
#pragma unroll
            for (int i = 0; i < 4; i++)
                wmma::load_matrix_sync(a[i], &As[cur][warpRow * 64 + i * 16][kk], LDA);
#pragma unroll
            for (int j = 0; j < 2; j++)
                wmma::load_matrix_sync(b[j], &Bs[cur][kk][warpCol * 32 + j * 16], LDB);
#pragma unroll
            for (int i = 0; i < 4; i++)
#pragma unroll
                for (int j = 0; j < 2; j++)
                    wmma::mma_sync(acc[i][j], a[i], b[j], acc[i][j]);
        }
        __syncthreads();
    }

#pragma unroll
    for (int i = 0; i < 4; i++)
#pragma unroll
        for (int j = 0; j < 2; j++) {
            int r = rowBase + warpRow * 64 + i * 16;
            int c = colBase + warpCol * 32 + j * 16;
            wmma::store_matrix_sync(&C[(size_t)r * NB + c], acc[i][j], NB, wmma::mem_row_major);
        }
}

// ---------------- per-graph mean readout (graph_ids sorted) ----------------
__global__ void readout_kernel(const int* __restrict__ gid,
                               const float* __restrict__ b2, int n) {
    const int g = blockIdx.x;
    const int t = threadIdx.x;  // 256 threads, one per feature column
    __shared__ int s_lo, s_hi;
    if (t == 0) {
        int lo = 0, hi = n;
        while (lo < hi) { int m = (lo + hi) >> 1; if (gid[m] < g) lo = m + 1; else hi = m; }
        s_lo = lo;
        hi = n;
        while (lo < hi) { int m = (lo + hi) >> 1; if (gid[m] <= g) lo = m + 1; else hi = m; }
        s_hi = lo;
    }
    __syncthreads();
    const float b = b2[t];
    float acc = 0.f;
    for (int nd = s_lo; nd < s_hi; nd++)
        acc += fmaxf(g_h2[(size_t)nd * DH + t] + b, 0.f);
    float cnt = (float)(s_hi - s_lo);
    g_hg[g * DH + t] = acc / fmaxf(cnt, 1.f);
}

// ---------------- final MLP head: out = (hg@Wr1+br1)@Wr2+br2 ----------------
__global__ void mlp_kernel(const float* __restrict__ Wr1, const float* __restrict__ br1,
                           const float* __restrict__ Wr2, const float* __restrict__ br2,
                           float* __restrict__ out) {
    const int g = blockIdx.x;
    const int t = threadIdx.x;  // 128 threads (H2)
    float acc = br1[t];
    const float* hg = &g_hg[g * DH];
    for (int k = 0; k < DH; k++) acc += hg[k] * Wr1[k * H2D + t];
    __shared__ float red[H2D];
    red[t] = acc * Wr2[t];
    __syncthreads();
    for (int s = H2D / 2; s > 0; s >>= 1) {
        if (t < s) red[t] += red[t + s];
        __syncthreads();
    }
    if (t == 0) out[g] = red[0] + br2[0];
}

// ---------------- launch ----------------
extern "C" void kernel_launch(void* const* d_in, const int* in_sizes, int n_in,
                              void* d_out, int out_size) {
    const float* h   = (const float*)d_in[0];
    const int*   src = (const int*)d_in[1];
    const int*   dst = (const int*)d_in[2];
    const int*   gid = (const int*)d_in[3];
    const float* W1  = (const float*)d_in[4];
    const float* b1  = (const float*)d_in[5];
    const float* W2  = (const float*)d_in[6];
    const float* b2  = (const float*)d_in[7];
    const float* Wr1 = (const float*)d_in[8];
    const float* br1 = (const float*)d_in[9];
    const float* Wr2 = (const float*)d_in[10];
    const float* br2 = (const float*)d_in[11];
    float* out = (float*)d_out;

    const int N = in_sizes[0] / DIN;   // 50000
    const int E = in_sizes[1];         // 800000

    float *pa1, *ph1, *pa2, *ph2, *pw1, *pw2;
    cudaGetSymbolAddress((void**)&pa1, g_a1);
    cudaGetSymbolAddress((void**)&ph1, g_h1);
    cudaGetSymbolAddress((void**)&pa2, g_a2);
    cudaGetSymbolAddress((void**)&ph2, g_h2);
    cudaGetSymbolAddress((void**)&pw1, g_w1r);
    cudaGetSymbolAddress((void**)&pw2, g_w2r);

    // 1) CSR build (dst-indexed) + weight tf32 pre-rounding
    zero_deg_kernel<<<(N + 255) / 256, 256>>>(N);
    hist_kernel<<<(E + 255) / 256, 256>>>(dst, E);
    round_w_kernel<<<(DIN * DH + 255) / 256, 256>>>(W1, pw1, DIN * DH);
    round_w_kernel<<<(DH * DH + 255) / 256, 256>>>(W2, pw2, DH * DH);
    scan_kernel<<<1, 1024>>>(N);
    fill_kernel<<<(E + 255) / 256, 256>>>(src, dst, E);

    // 2) layer 1: mean-agg then tf32 GEMM  [N,128]@[128,256]
    agg_kernel<DIN, 0><<<(NN * 32 + 255) / 256, 256>>>(h, nullptr, pa1);
    {
        dim3 grid(DH / 128, NN_PAD / 128);
        gemm_tf32_kernel<DIN><<<grid, 256>>>(pa1, pw1, ph1);
    }

    // 3) layer 2: mean-agg (fused relu(x+b1)) then tf32 GEMM  [N,256]@[256,256]
    agg_kernel<DH, 1><<<(NN * 32 + 255) / 256, 256>>>(ph1, b1, pa2);
    {
        dim3 grid(DH / 128, NN_PAD / 128);
        gemm_tf32_kernel<DH><<<grid, 256>>>(pa2, pw2, ph2);
    }

    // 4) per-graph mean readout (fused relu(x+b2)) + MLP head
    readout_kernel<<<NG, DH>>>(gid, b2, N);
    mlp_kernel<<<NG, H2D>>>(Wr1, br1, Wr2, br2, out);
}